// round 10
// baseline (speedup 1.0000x reference)
#include <cuda_runtime.h>
#include <math.h>
#include <float.h>
#include <stdint.h>

#define VOCAB 32000
#define HID   1024
#define BEAM  16
#define TSTEPS 16
#define NCHUNK 8    // topk scan chunks per beam
#define CHSZ  4000  // VOCAB / NCHUNK

#define G2_COLS 128 // columns per gemm2 block
#define G2_KS   8   // k-splits inside a gemm2 block
#define G2_KC   128 // k per split
#define G2_SMEM 65536

// ---------------- scratch (device globals; no allocation) ----------------
__device__ float g_logits[BEAM][VOCAB];          // final logits (2 MB)
__device__ float g_stateA[BEAM][HID];
__device__ float g_stateB[BEAM][HID];
__device__ float g_part1[64][BEAM][HID];         // gemm1 partials (4 MB)
__device__ float g_cv[BEAM][NCHUNK][16];         // per-chunk top16 values (compare keys)
__device__ int   g_ci[BEAM][NCHUNK][16];
__device__ float g_cm[BEAM][NCHUNK];             // per-chunk lse max
__device__ float g_cs[BEAM][NCHUNK];             // per-chunk lse sum
__device__ float g_beam_lps[BEAM];
__device__ int   g_beam_seq[TSTEPS][BEAM];
__device__ float g_beam_seq_lp[TSTEPS][BEAM];
__device__ int   g_sel_c[BEAM];
__device__ int   g_sel_q[BEAM];
__device__ unsigned g_cnt[TSTEPS];               // scan completion counters
__device__ unsigned g_g1cnt[TSTEPS];             // gemm1 completion counters
__device__ unsigned g_hcnt[TSTEPS];              // h-ready counters

// ---------------- helpers ----------------
__device__ __forceinline__ bool better(float va, int ia, float vb, int ib) {
    return (va > vb) || (va == vb && ia < ib);
}
__device__ __forceinline__ unsigned long long pack2(float x, float y) {
    unsigned long long r;
    asm("mov.b64 %0, {%1, %2};" : "=l"(r)
        : "r"(__float_as_uint(x)), "r"(__float_as_uint(y)));
    return r;
}
__device__ __forceinline__ void unpack2(unsigned long long v, float &x, float &y) {
    unsigned int a, b;
    asm("mov.b64 {%0, %1}, %2;" : "=r"(a), "=r"(b) : "l"(v));
    x = __uint_as_float(a); y = __uint_as_float(b);
}
__device__ __forceinline__ void fma2(unsigned long long &d, unsigned long long a,
                                     unsigned long long b) {
    asm("fma.rn.f32x2 %0, %1, %2, %3;" : "=l"(d) : "l"(a), "l"(b), "l"(d));
}
__device__ __forceinline__ float tanh_acc(float x) {
    float ax = fabsf(x);
    float e  = __expf(2.0f * ax);
    float r  = 1.0f - 2.0f / (e + 1.0f);
    return copysignf(r, x);
}
__device__ __forceinline__ void merge16(const float* av, const int* ai,
                                        const float* bv, const int* bi,
                                        float* ov, int* oi) {
    int pa = 0, pb = 0;
#pragma unroll
    for (int k = 0; k < 16; k++) {
        float x1 = av[pa]; int i1 = ai[pa];
        float x2 = bv[pb]; int i2 = bi[pb];
        bool ta = better(x1, i1, x2, i2);
        ov[k] = ta ? x1 : x2; oi[k] = ta ? i1 : i2;
        pa += ta; pb += !ta;
    }
}

// ---------------- init ----------------
__global__ void init_kernel(const float* __restrict__ state) {
    int i = blockIdx.x * 256 + threadIdx.x;
    if (i < BEAM * HID) ((float*)g_stateA)[i] = state[i];
    if (i < BEAM) g_beam_lps[i] = 0.f;
    if (i < TSTEPS) { g_cnt[i] = 0u; g_g1cnt[i] = 0u; g_hcnt[i] = 0u; }
}

// ---------------- scan + fused last-block merge/select (unchanged from R7) ----------------
// grid (NCHUNK, BEAM) x 256
__global__ void __launch_bounds__(256) topk_scan(const float* __restrict__ logprobs0, int t) {
    __shared__ float sv[256][16];
    __shared__ int   si[256][16];
    __shared__ float rm[256], rs[256];
    __shared__ int   isLast;
    int chunk = blockIdx.x, b = blockIdx.y, tid = threadIdx.x;
    int base = chunk * CHSZ, end = base + CHSZ;

    const float* src = (t == 0) ? (logprobs0 + (size_t)b * VOCAB) : g_logits[b];

    float lv[16]; int li[16];
#pragma unroll
    for (int j = 0; j < 16; j++) { lv[j] = -INFINITY; li[j] = 0x7fffffff; }
    float m = -INFINITY, s = 0.f;

    for (int i = base + tid; i < end; i += 256) {
        float x = src[i];
        if (x > m) { s = s * __expf(m - x) + 1.f; m = x; }
        else       { s += __expf(x - m); }
        float v = (i == VOCAB - 1) ? x - 1000.f : x;  // lpf tweak (compare key)
        if (better(v, i, lv[15], li[15])) {
#pragma unroll
            for (int j = 15; j >= 1; j--) {
                bool cj  = better(v, i, lv[j],     li[j]);
                bool cjm = better(v, i, lv[j - 1], li[j - 1]);
                float nv = cjm ? lv[j - 1] : v;
                int   ni = cjm ? li[j - 1] : i;
                lv[j] = cj ? nv : lv[j];
                li[j] = cj ? ni : li[j];
            }
            bool c0 = better(v, i, lv[0], li[0]);
            if (c0) { lv[0] = v; li[0] = i; }
        }
    }
#pragma unroll
    for (int j = 0; j < 16; j++) { sv[tid][j] = lv[j]; si[tid][j] = li[j]; }
    rm[tid] = m; rs[tid] = s;
    __syncthreads();

    for (int stride = 128; stride >= 1; stride >>= 1) {
        if (tid < stride) {
            float ov[16]; int oi[16];
            merge16(sv[tid], si[tid], sv[tid + stride], si[tid + stride], ov, oi);
#pragma unroll
            for (int j = 0; j < 16; j++) { sv[tid][j] = ov[j]; si[tid][j] = oi[j]; }
            float m2 = rm[tid + stride], s2 = rs[tid + stride];
            float m1 = rm[tid], s1 = rs[tid];
            float M = fmaxf(m1, m2);
            rs[tid] = s1 * __expf(m1 - M) + s2 * __expf(m2 - M);
            rm[tid] = M;
        }
        __syncthreads();
    }
    if (tid < 16) {
        g_cv[b][chunk][tid] = sv[0][tid];
        g_ci[b][chunk][tid] = si[0][tid];
    }
    if (tid == 0) { g_cm[b][chunk] = rm[0]; g_cs[b][chunk] = rs[0]; }
    __syncthreads();

    // ---- last-block election ----
    if (tid == 0) {
        __threadfence();
        unsigned v = atomicAdd(&g_cnt[t], 1u);
        isLast = (v == (unsigned)(NCHUNK * BEAM - 1));
    }
    __syncthreads();
    if (!isLast) return;
    __threadfence();   // acquire: all other blocks' writes visible

    // ---- merge + normalize + global select (aliased onto scan smem) ----
    float* F = &sv[0][0];     // 4096 floats
    int*   I = &si[0][0];     // 4096 ints
    float (*Av)[NCHUNK][16]     = (float (*)[NCHUNK][16])F;              // 2048
    float (*Bv)[NCHUNK / 2][16] = (float (*)[NCHUNK / 2][16])(F + 2048); // 1024
    float (*tv)[16]             = (float (*)[16])(F + 3072);             // 256
    float* cand = F + 3328;                                              // 256
    float* lzM  = F + 3584; float* lzL = F + 3600;
    float* selv = F + 3616; float* r_s = F + 3632; float* p_s = F + 3648;
    int (*Ai)[NCHUNK][16]     = (int (*)[NCHUNK][16])I;
    int (*Bi)[NCHUNK / 2][16] = (int (*)[NCHUNK / 2][16])(I + 2048);
    int (*ti)[16]             = (int (*)[16])(I + 3072);
    int* seli = I + 3328; int* q_s = I + 3344; int* c_s = I + 3360;
    float* oldlp  = rm;          // 256 floats
    int*   oldseq = (int*)rs;    // 256 ints

    for (int idx = tid; idx < BEAM * NCHUNK * 16; idx += 256) {
        F[idx] = __ldcg(&((const float*)g_cv)[idx]);
        I[idx] = __ldcg(&((const int*)g_ci)[idx]);
    }
    for (int idx = tid; idx < t * BEAM; idx += 256) {
        oldseq[idx] = ((const int*)g_beam_seq)[idx];
        oldlp[idx]  = ((const float*)g_beam_seq_lp)[idx];
    }
    __syncthreads();

    if (tid < BEAM * 4) {
        int bb = tid >> 2, j = tid & 3;
        merge16(Av[bb][2*j], Ai[bb][2*j], Av[bb][2*j+1], Ai[bb][2*j+1],
                Bv[bb][j], Bi[bb][j]);
    }
    if (tid >= 128 && tid < 128 + BEAM) {
        int bb = tid - 128;
        float M = __ldcg(&g_cm[bb][0]);
#pragma unroll
        for (int c = 1; c < NCHUNK; c++) M = fmaxf(M, __ldcg(&g_cm[bb][c]));
        float S = 0.f;
#pragma unroll
        for (int c = 0; c < NCHUNK; c++)
            S += __ldcg(&g_cs[bb][c]) * __expf(__ldcg(&g_cm[bb][c]) - M);
        lzM[bb] = M; lzL[bb] = logf(S);
    }
    __syncthreads();
    if (tid < BEAM * 2) {
        int bb = tid >> 1, j = tid & 1;
        merge16(Bv[bb][2*j], Bi[bb][2*j], Bv[bb][2*j+1], Bi[bb][2*j+1],
                Av[bb][j], Ai[bb][j]);
    }
    __syncthreads();
    if (tid < BEAM) {
        merge16(Av[tid][0], Ai[tid][0], Av[tid][1], Ai[tid][1],
                Bv[tid][0], Bi[tid][0]);
    }
    __syncthreads();

    {
        int bb = tid >> 4, j = tid & 15;
        float v = Bv[bb][0][j];
        int   i = Bi[bb][0][j];
        float outv;
        if (t == 0) {
            outv = v;   // input already log_softmax'd; bitwise-exact
        } else {
            float mm = lzM[bb], lse = lzL[bb];
            if (i == VOCAB - 1) outv = ((__ldcg(&g_logits[bb][VOCAB - 1]) - mm) - lse) - 1000.f;
            else                outv = (v - mm) - lse;
        }
        tv[bb][j] = outv; ti[bb][j] = i;
    }
    __syncthreads();

    {
        int qi = tid >> 4, j = tid & 15;
        float cp = g_beam_lps[qi] + tv[qi][j];
        if (t == 0 && qi != 0) cp = -INFINITY;
        cand[tid] = cp;
    }
    __syncthreads();

    if (tid < 32) {
        for (int r = 0; r < 16; r++) {
            float bv = -INFINITY; int bi = 0x7fffffff;
#pragma unroll
            for (int k2 = 0; k2 < 8; k2++) {
                int idx = tid * 8 + k2;
                float v = cand[idx];
                if (better(v, idx, bv, bi)) { bv = v; bi = idx; }
            }
#pragma unroll
            for (int off = 16; off >= 1; off >>= 1) {
                float ov = __shfl_down_sync(0xffffffffu, bv, off);
                int   oi = __shfl_down_sync(0xffffffffu, bi, off);
                if (better(ov, oi, bv, bi)) { bv = ov; bi = oi; }
            }
            bv = __shfl_sync(0xffffffffu, bv, 0);
            bi = __shfl_sync(0xffffffffu, bi, 0);
            if (tid == 0) { selv[r] = bv; seli[r] = bi; cand[bi] = -INFINITY; }
            __syncwarp();
        }
        if (tid < 16) {
            int fi = seli[tid];
            int q = fi >> 4, col = fi & 15;
            int c = ti[q][col];
            float rr = tv[q][col];
            q_s[tid] = q; c_s[tid] = c; r_s[tid] = rr;
            bool done = (c == 0) || (t == TSTEPS - 1);
            p_s[tid] = done ? -1000.f : selv[tid];
        }
    }
    __syncthreads();

    for (int idx = tid; idx < t * BEAM; idx += 256) {
        int row = idx >> 4, col = idx & 15;
        ((int*)g_beam_seq)[idx]      = oldseq[row * 16 + q_s[col]];
        ((float*)g_beam_seq_lp)[idx] = oldlp[row * 16 + q_s[col]];
    }
    if (tid < 16) {
        g_beam_seq[t][tid]    = c_s[tid];
        g_beam_seq_lp[t][tid] = r_s[tid];
        g_beam_lps[tid]       = p_s[tid];
        g_sel_c[tid] = c_s[tid];
        g_sel_q[tid] = q_s[tid];
    }
}

// ---------------- fused step kernel: gemm1 + reduce/tanh + gemm2 ----------------
// grid 250 x 256, 64KB dynamic smem, 2 CTAs/SM (all 250 co-resident on 296 slots
// -> grid-wide spin flags are deadlock-free). All accumulation orders are
// byte-identical to the R7 three-kernel pipeline.
__global__ void __launch_bounds__(256, 2) step_kernel(const float* __restrict__ embed,
                                                      const float* __restrict__ Wih,
                                                      const float* __restrict__ Whh,
                                                      const float* __restrict__ bias,
                                                      const float* __restrict__ Wout, int t) {
    extern __shared__ char smem_raw[];
    const float (*state)[HID] = (t & 1) ? g_stateB : g_stateA;
    float (*outh)[HID]        = (t & 1) ? g_stateA : g_stateB;
    int bx = blockIdx.x, tid = threadIdx.x;

    // ======== phase A: gemm1 partials (blocks 0..127; 2 halves x 2 passes = 512 R7 tiles) ====
    if (bx < 128) {
        float (*xsl)[16] = ((float (*)[16])smem_raw) + (tid >> 7) * 32;   // per-half [32][16]
        int tl = tid & 127;
#pragma unroll
        for (int pass = 0; pass < 2; pass++) {
            int unit = pass * 256 + bx * 2 + (tid >> 7);   // R7 (cb,ks): unit = cb*64 + ks
            int cb = unit >> 6;
            int ks = unit & 63;
            int o = cb * 128 + tl;
            bool isHH = ks >= 32;
            const float* W = isHH ? Whh : Wih;
            int k0 = (ks & 31) * 32;

            float w[32];
            {
                const float* wp = W + (size_t)k0 * HID + o;
#pragma unroll
                for (int kk = 0; kk < 32; kk++) w[kk] = wp[(size_t)kk * HID];
            }
            for (int idx = tl; idx < BEAM * 32; idx += 128) {
                int bb = idx >> 5, kk = idx & 31;
                float xv = isHH ? state[g_sel_q[bb]][k0 + kk]
                                : embed[(size_t)g_sel_c[bb] * HID + k0 + kk];
                xsl[kk][bb] = xv;
            }
            __syncthreads();

            unsigned long long acc[8];
#pragma unroll
            for (int p = 0; p < 8; p++) acc[p] = 0ull;
#pragma unroll
            for (int kk = 0; kk < 32; kk++) {
                unsigned long long w2 = pack2(w[kk], w[kk]);
#pragma unroll
                for (int p = 0; p < 8; p++) {
                    unsigned long long x = *(const unsigned long long*)&xsl[kk][2 * p];
                    fma2(acc[p], x, w2);
                }
            }
#pragma unroll
            for (int p = 0; p < 8; p++) {
                float a, b2; unpack2(acc[p], a, b2);
                g_part1[ks][2 * p][o]     = a;
                g_part1[ks][2 * p + 1][o] = b2;
            }
            __syncthreads();   // xsl dead before next pass refill
        }
        __threadfence();       // release this block's partial writes
        __syncthreads();
        if (tid == 0) atomicAdd(&g_g1cnt[t], 1u);
    }

    // ======== phase R: reduce + tanh (blocks 0..7, one 128-col group each) ========
    if (bx < 8) {
        if (tid == 0) {
            while (((volatile unsigned*)g_g1cnt)[t] < 128u) __nanosleep(64);
        }
        __syncthreads();
        __threadfence();       // acquire: all partials visible

        int oc = tid & 127;
        int bb0 = (tid >> 7) * 8;
        int oo = bx * 128 + oc;
        float sih[8], shh[8];
#pragma unroll
        for (int j = 0; j < 8; j++) { sih[j] = 0.f; shh[j] = 0.f; }
#pragma unroll 4
        for (int ks = 0; ks < 32; ks++) {
#pragma unroll
            for (int j = 0; j < 8; j++) sih[j] += __ldcg(&g_part1[ks][bb0 + j][oo]);
        }
#pragma unroll 4
        for (int ks = 32; ks < 64; ks++) {
#pragma unroll
            for (int j = 0; j < 8; j++) shh[j] += __ldcg(&g_part1[ks][bb0 + j][oo]);
        }
        float bv = bias[oo];
#pragma unroll
        for (int j = 0; j < 8; j++)
            outh[bb0 + j][oo] = tanh_acc((sih[j] + shh[j]) + bv);

        __threadfence();       // release h writes
        __syncthreads();
        if (tid == 0) atomicAdd(&g_hcnt[t], 1u);
    }

    // ======== wait for h (all blocks) ========
    if (tid == 0) {
        while (((volatile unsigned*)g_hcnt)[t] < 8u) __nanosleep(64);
    }
    __syncthreads();
    __threadfence();           // acquire before reading outh

    // ======== phase B: output projection (exact R7 gemm2 body) ========
    {
        float (*xs)[16] = (float (*)[16])smem_raw;            // [1024][16] = 64KB
        int cb  = bx;
        int ksp  = tid >> 5;      // 0..7
        int colg = tid & 31;      // 0..31

        for (int idx = tid; idx < 4096; idx += 256) {
            int b = idx & 15, k4 = idx >> 4;
            float4 v = __ldcg((const float4*)&outh[b][k4 * 4]);
            xs[k4 * 4 + 0][b] = v.x; xs[k4 * 4 + 1][b] = v.y;
            xs[k4 * 4 + 2][b] = v.z; xs[k4 * 4 + 3][b] = v.w;
        }
        __syncthreads();

        int col = cb * G2_COLS + colg * 4;
        int k0  = ksp * G2_KC;
        unsigned long long acc[4][8];
#pragma unroll
        for (int c = 0; c < 4; c++)
#pragma unroll
            for (int p = 0; p < 8; p++) acc[c][p] = 0ull;

        const float* wp = Wout + (size_t)k0 * VOCAB + col;
        float4 wreg[4];
#pragma unroll
        for (int p = 0; p < 4; p++) wreg[p] = *(const float4*)(wp + (size_t)p * VOCAB);

        for (int kg = 0; kg < G2_KC; kg += 4) {
#pragma unroll
            for (int p = 0; p < 4; p++) {
                float4 w = wreg[p];
                if (kg + 4 + p < G2_KC)
                    wreg[p] = *(const float4*)(wp + (size_t)(kg + 4 + p) * VOCAB);
                int kk = k0 + kg + p;
                unsigned long long w0 = pack2(w.x, w.x);
                unsigned long long w1 = pack2(w.y, w.y);
                unsigned long long w2 = pack2(w.z, w.z);
                unsigned long long w3 = pack2(w.w, w.w);
                const ulonglong2* xr = (const ulonglong2*)xs[kk];
                ulonglong2 qa = xr[0], qb = xr[1], qc = xr[2], qd = xr[3];
                fma2(acc[0][0], qa.x, w0); fma2(acc[1][0], qa.x, w1);
                fma2(acc[2][0], qa.x, w2); fma2(acc[3][0], qa.x, w3);
                fma2(acc[0][1], qa.y, w0); fma2(acc[1][1], qa.y, w1);
                fma2(acc[2][1], qa.y, w2); fma2(acc[3][1], qa.y, w3);
                fma2(acc[0][2], qb.x, w0); fma2(acc[1][2], qb.x, w1);
                fma2(acc[2][2], qb.x, w2); fma2(acc[3][2], qb.x, w3);
                fma2(acc[0][3], qb.y, w0); fma2(acc[1][3], qb.y, w1);
                fma2(acc[2][3], qb.y, w2); fma2(acc[3][3], qb.y, w3);
                fma2(acc[0][4], qc.x, w0); fma2(acc[1][4], qc.x, w1);
                fma2(acc[2][4], qc.x, w2); fma2(acc[3][4], qc.x, w3);
                fma2(acc[0][5], qc.y, w0); fma2(acc[1][5], qc.y, w1);
                fma2(acc[2][5], qc.y, w2); fma2(acc[3][5], qc.y, w3);
                fma2(acc[0][6], qd.x, w0); fma2(acc[1][6], qd.x, w1);
                fma2(acc[2][6], qd.x, w2); fma2(acc[3][6], qd.x, w3);
                fma2(acc[0][7], qd.y, w0); fma2(acc[1][7], qd.y, w1);
                fma2(acc[2][7], qd.y, w2); fma2(acc[3][7], qd.y, w3);
            }
        }
        __syncthreads();   // xs done; reuse smem as reduce buffer

        float (*red)[BEAM][G2_COLS] = (float (*)[BEAM][G2_COLS])smem_raw;  // [8][16][128]
#pragma unroll
        for (int c = 0; c < 4; c++) {
#pragma unroll
            for (int p = 0; p < 8; p++) {
                float a, b2; unpack2(acc[c][p], a, b2);
                red[ksp][2 * p][colg * 4 + c]     = a;
                red[ksp][2 * p + 1][colg * 4 + c] = b2;
            }
        }
        __syncthreads();

        for (int idx = tid; idx < G2_COLS * BEAM; idx += 256) {
            int b = idx >> 7, c = idx & 127;
            float s = 0.f;
#pragma unroll
            for (int k = 0; k < G2_KS; k++) s += red[k][b][c];
            g_logits[b][cb * G2_COLS + c] = s;
        }
    }
}

// ---------------- pack outputs ----------------
__global__ void output_kernel(float* __restrict__ out, int out_size) {
    int i = blockIdx.x * 256 + threadIdx.x;
    if (i >= out_size) return;
    if (i < TSTEPS * BEAM) {
        out[i] = (float)((const int*)g_beam_seq)[i];
    } else if (i < 2 * TSTEPS * BEAM) {
        out[i] = ((const float*)g_beam_seq_lp)[i - TSTEPS * BEAM];
    } else if (i < 2 * TSTEPS * BEAM + BEAM) {
        out[i] = g_beam_lps[i - 2 * TSTEPS * BEAM];
    } else {
        out[i] = 0.f;
    }
}

extern "C" void kernel_launch(void* const* d_in, const int* in_sizes, int n_in,
                              void* d_out, int out_size) {
    const float* state    = (const float*)d_in[0];
    const float* logprobs = (const float*)d_in[1];
    const float* embed    = (const float*)d_in[2];
    const float* W_ih     = (const float*)d_in[3];
    const float* W_hh     = (const float*)d_in[4];
    const float* b        = (const float*)d_in[5];
    const float* W_out    = (const float*)d_in[6];

    cudaFuncSetAttribute(step_kernel,
                         cudaFuncAttributeMaxDynamicSharedMemorySize, G2_SMEM);

    init_kernel<<<64, 256>>>(state);
    for (int t = 0; t < TSTEPS; t++) {
        dim3 gs(NCHUNK, BEAM);
        topk_scan<<<gs, 256>>>(logprobs, t);   // fused merge+select in last block
        if (t < TSTEPS - 1) {
            step_kernel<<<250, 256, G2_SMEM>>>(embed, W_ih, W_hh, b, W_out, t);
        }
    }
    int nblk = (out_size + 255) / 256;
    if (nblk < 1) nblk = 1;
    output_kernel<<<nblk, 256>>>((float*)d_out, out_size);
}

// round 11
// speedup vs baseline: 1.2847x; 1.2847x over previous
#include <cuda_runtime.h>
#include <math.h>
#include <float.h>
#include <stdint.h>

#define VOCAB 32000
#define HID   1024
#define BEAM  16
#define TSTEPS 16
#define NCHUNK 8    // topk scan chunks per beam
#define CHSZ  4000  // VOCAB / NCHUNK

#define G2_COLS 128 // columns per gemm2 block
#define G2_KS   8   // k-splits inside a gemm2 block
#define G2_KC   128 // k per split
#define G2_SMEM 65536

// ---------------- scratch (device globals; no allocation) ----------------
__device__ float g_logits[BEAM][VOCAB];          // final logits (2 MB)
__device__ float g_stateA[BEAM][HID];
__device__ float g_stateB[BEAM][HID];
__device__ float g_part1[64][BEAM][HID];         // gemm1 partials (4 MB)
__device__ float g_cv[BEAM][NCHUNK][16];         // per-chunk top16 values (compare keys)
__device__ int   g_ci[BEAM][NCHUNK][16];
__device__ float g_cm[BEAM][NCHUNK];             // per-chunk lse max
__device__ float g_cs[BEAM][NCHUNK];             // per-chunk lse sum
__device__ float g_beam_lps[BEAM];
__device__ int   g_beam_seq[TSTEPS][BEAM];
__device__ float g_beam_seq_lp[TSTEPS][BEAM];
__device__ int   g_sel_c[BEAM];
__device__ int   g_sel_q[BEAM];
__device__ unsigned g_cnt[TSTEPS];               // scan completion counters

// ---------------- helpers ----------------
__device__ __forceinline__ bool better(float va, int ia, float vb, int ib) {
    return (va > vb) || (va == vb && ia < ib);
}
__device__ __forceinline__ unsigned long long pack2(float x, float y) {
    unsigned long long r;
    asm("mov.b64 %0, {%1, %2};" : "=l"(r)
        : "r"(__float_as_uint(x)), "r"(__float_as_uint(y)));
    return r;
}
__device__ __forceinline__ void unpack2(unsigned long long v, float &x, float &y) {
    unsigned int a, b;
    asm("mov.b64 {%0, %1}, %2;" : "=r"(a), "=r"(b) : "l"(v));
    x = __uint_as_float(a); y = __uint_as_float(b);
}
__device__ __forceinline__ void fma2(unsigned long long &d, unsigned long long a,
                                     unsigned long long b) {
    asm("fma.rn.f32x2 %0, %1, %2, %3;" : "=l"(d) : "l"(a), "l"(b), "l"(d));
}
__device__ __forceinline__ float tanh_acc(float x) {
    float ax = fabsf(x);
    float e  = __expf(2.0f * ax);
    float r  = 1.0f - 2.0f / (e + 1.0f);
    return copysignf(r, x);
}
__device__ __forceinline__ void merge16(const float* av, const int* ai,
                                        const float* bv, const int* bi,
                                        float* ov, int* oi) {
    int pa = 0, pb = 0;
#pragma unroll
    for (int k = 0; k < 16; k++) {
        float x1 = av[pa]; int i1 = ai[pa];
        float x2 = bv[pb]; int i2 = bi[pb];
        bool ta = better(x1, i1, x2, i2);
        ov[k] = ta ? x1 : x2; oi[k] = ta ? i1 : i2;
        pa += ta; pb += !ta;
    }
}

// ---------------- init ----------------
__global__ void init_kernel(const float* __restrict__ state) {
    int i = blockIdx.x * 256 + threadIdx.x;
    if (i < BEAM * HID) ((float*)g_stateA)[i] = state[i];
    if (i < BEAM) g_beam_lps[i] = 0.f;
    if (i < TSTEPS) g_cnt[i] = 0u;
}

// ---------------- scan: packed-key iterative block-max top16 + fused select ----------------
// grid (NCHUNK, BEAM) x 256
__global__ void __launch_bounds__(256) topk_scan(const float* __restrict__ logprobs0, int t) {
    __shared__ unsigned long long wmax[8];
    __shared__ unsigned long long bmax_s;
    __shared__ float rm8[8], rs8[8];
    __shared__ int   isLast;
    // select-phase smem (last block only)
    __shared__ float Av[BEAM][NCHUNK][16];
    __shared__ int   Ai[BEAM][NCHUNK][16];
    __shared__ float Bv[BEAM][NCHUNK / 2][16];
    __shared__ int   Bi[BEAM][NCHUNK / 2][16];
    __shared__ float tv[BEAM][16];
    __shared__ int   ti[BEAM][16];
    __shared__ float lzM[BEAM], lzL[BEAM];
    __shared__ float cand[256];
    __shared__ float selv[16]; __shared__ int seli[16];
    __shared__ int   q_s[16], c_s[16];
    __shared__ float r_s[16], p_s[16];
    __shared__ int   oldseq[TSTEPS * BEAM];
    __shared__ float oldlp[TSTEPS * BEAM];

    int chunk = blockIdx.x, b = blockIdx.y, tid = threadIdx.x;
    int base = chunk * CHSZ;
    const float* src = (t == 0) ? (logprobs0 + (size_t)b * VOCAB) : g_logits[b];

    // ---- load elements as sortable packed keys; online lse ----
    unsigned long long key[16];
    float m = -INFINITY, s = 0.f;
#pragma unroll
    for (int j = 0; j < 16; j++) {
        int off = j * 256 + tid;
        key[j] = 0ull;
        if (off < CHSZ) {
            int i = base + off;
            float x = src[i];
            if (x > m) { s = s * __expf(m - x) + 1.f; m = x; }
            else       { s += __expf(x - m); }
            float v = (i == VOCAB - 1) ? x - 1000.f : x;   // lpf tweak (compare key)
            unsigned u  = __float_as_uint(v);
            unsigned su = (u & 0x80000000u) ? ~u : (u | 0x80000000u);
            key[j] = ((unsigned long long)su << 32) | (unsigned)(~(unsigned)i);
        }
    }

    // ---- lse: warp butterfly + cross-warp combine ----
    {
#pragma unroll
        for (int off = 16; off >= 1; off >>= 1) {
            float m2 = __shfl_xor_sync(0xffffffffu, m, off);
            float s2 = __shfl_xor_sync(0xffffffffu, s, off);
            float M = fmaxf(m, m2);
            s = s * __expf(m - M) + s2 * __expf(m2 - M);
            m = M;
        }
        if ((tid & 31) == 0) { rm8[tid >> 5] = m; rs8[tid >> 5] = s; }
    }
    __syncthreads();
    if (tid == 0) {
        float M = rm8[0], S = rs8[0];
#pragma unroll
        for (int w = 1; w < 8; w++) {
            float m2 = rm8[w], s2 = rs8[w];
            float MM = fmaxf(M, m2);
            S = S * __expf(M - MM) + s2 * __expf(m2 - MM);
            M = MM;
        }
        g_cm[b][chunk] = M; g_cs[b][chunk] = S;
    }

    // ---- 16 rounds of exact block max (key order == better()) ----
    for (int r = 0; r < 16; r++) {
        unsigned long long lmax = key[0]; int lj = 0;
#pragma unroll
        for (int j = 1; j < 16; j++) if (key[j] > lmax) { lmax = key[j]; lj = j; }
        unsigned long long wm = lmax;
#pragma unroll
        for (int off = 16; off >= 1; off >>= 1) {
            unsigned long long o = __shfl_xor_sync(0xffffffffu, wm, off);
            if (o > wm) wm = o;
        }
        if ((tid & 31) == 0) wmax[tid >> 5] = wm;
        __syncthreads();
        if (tid == 0) {
            unsigned long long bm = wmax[0];
#pragma unroll
            for (int w = 1; w < 8; w++) if (wmax[w] > bm) bm = wmax[w];
            bmax_s = bm;
            unsigned su = (unsigned)(bm >> 32);
            unsigned u  = (su & 0x80000000u) ? (su ^ 0x80000000u) : ~su;
            g_cv[b][chunk][r] = __uint_as_float(u);
            g_ci[b][chunk][r] = (int)(~(unsigned)(bm & 0xFFFFFFFFu));
        }
        __syncthreads();
        if (lmax == bmax_s) key[lj] = 0ull;   // unique owner (index in key)
    }

    // ---- last-block election ----
    if (tid == 0) {
        __threadfence();
        unsigned v = atomicAdd(&g_cnt[t], 1u);
        isLast = (v == (unsigned)(NCHUNK * BEAM - 1));
    }
    __syncthreads();
    if (!isLast) return;
    __threadfence();   // acquire: all other blocks' writes visible

    // ---- merge + normalize + global select (exact R7 logic) ----
    for (int idx = tid; idx < BEAM * NCHUNK * 16; idx += 256) {
        ((float*)Av)[idx] = __ldcg(&((const float*)g_cv)[idx]);
        ((int*)Ai)[idx]   = __ldcg(&((const int*)g_ci)[idx]);
    }
    for (int idx = tid; idx < t * BEAM; idx += 256) {
        oldseq[idx] = ((const int*)g_beam_seq)[idx];
        oldlp[idx]  = ((const float*)g_beam_seq_lp)[idx];
    }
    __syncthreads();

    if (tid < BEAM * 4) {
        int bb = tid >> 2, j = tid & 3;
        merge16(Av[bb][2*j], Ai[bb][2*j], Av[bb][2*j+1], Ai[bb][2*j+1],
                Bv[bb][j], Bi[bb][j]);
    }
    if (tid >= 128 && tid < 128 + BEAM) {
        int bb = tid - 128;
        float M = __ldcg(&g_cm[bb][0]);
#pragma unroll
        for (int c = 1; c < NCHUNK; c++) M = fmaxf(M, __ldcg(&g_cm[bb][c]));
        float S = 0.f;
#pragma unroll
        for (int c = 0; c < NCHUNK; c++)
            S += __ldcg(&g_cs[bb][c]) * __expf(__ldcg(&g_cm[bb][c]) - M);
        lzM[bb] = M; lzL[bb] = logf(S);
    }
    __syncthreads();
    if (tid < BEAM * 2) {
        int bb = tid >> 1, j = tid & 1;
        merge16(Bv[bb][2*j], Bi[bb][2*j], Bv[bb][2*j+1], Bi[bb][2*j+1],
                Av[bb][j], Ai[bb][j]);
    }
    __syncthreads();
    if (tid < BEAM) {
        merge16(Av[tid][0], Ai[tid][0], Av[tid][1], Ai[tid][1],
                Bv[tid][0], Bi[tid][0]);
    }
    __syncthreads();

    {
        int bb = tid >> 4, j = tid & 15;
        float v = Bv[bb][0][j];
        int   i = Bi[bb][0][j];
        float outv;
        if (t == 0) {
            outv = v;   // input already log_softmax'd; bitwise-exact
        } else {
            float mm = lzM[bb], lse = lzL[bb];
            if (i == VOCAB - 1) outv = ((__ldcg(&g_logits[bb][VOCAB - 1]) - mm) - lse) - 1000.f;
            else                outv = (v - mm) - lse;
        }
        tv[bb][j] = outv; ti[bb][j] = i;
    }
    __syncthreads();

    {
        int qi = tid >> 4, j = tid & 15;
        float cp = g_beam_lps[qi] + tv[qi][j];
        if (t == 0 && qi != 0) cp = -INFINITY;
        cand[tid] = cp;
    }
    __syncthreads();

    if (tid < 32) {
        for (int r = 0; r < 16; r++) {
            float bv = -INFINITY; int bi = 0x7fffffff;
#pragma unroll
            for (int k2 = 0; k2 < 8; k2++) {
                int idx = tid * 8 + k2;
                float v = cand[idx];
                if (better(v, idx, bv, bi)) { bv = v; bi = idx; }
            }
#pragma unroll
            for (int off = 16; off >= 1; off >>= 1) {
                float ov = __shfl_down_sync(0xffffffffu, bv, off);
                int   oi = __shfl_down_sync(0xffffffffu, bi, off);
                if (better(ov, oi, bv, bi)) { bv = ov; bi = oi; }
            }
            bv = __shfl_sync(0xffffffffu, bv, 0);
            bi = __shfl_sync(0xffffffffu, bi, 0);
            if (tid == 0) { selv[r] = bv; seli[r] = bi; cand[bi] = -INFINITY; }
            __syncwarp();
        }
        if (tid < 16) {
            int fi = seli[tid];
            int q = fi >> 4, col = fi & 15;
            int c = ti[q][col];
            float rr = tv[q][col];
            q_s[tid] = q; c_s[tid] = c; r_s[tid] = rr;
            bool done = (c == 0) || (t == TSTEPS - 1);
            p_s[tid] = done ? -1000.f : selv[tid];
        }
    }
    __syncthreads();

    for (int idx = tid; idx < t * BEAM; idx += 256) {
        int row = idx >> 4, col = idx & 15;
        ((int*)g_beam_seq)[idx]      = oldseq[row * 16 + q_s[col]];
        ((float*)g_beam_seq_lp)[idx] = oldlp[row * 16 + q_s[col]];
    }
    if (tid < 16) {
        g_beam_seq[t][tid]    = c_s[tid];
        g_beam_seq_lp[t][tid] = r_s[tid];
        g_beam_lps[tid]       = p_s[tid];
        g_sel_c[tid] = c_s[tid];
        g_sel_q[tid] = q_s[tid];
    }
}

// ---------------- RNN cell GEMM (exact R7) ----------------
// grid (8, 64) x 128; weights prefetched to registers before smem barrier
__global__ void __launch_bounds__(128) gemm1_kernel(const float* __restrict__ embed,
                                                    const float* __restrict__ Wih,
                                                    const float* __restrict__ Whh, int t) {
    const float (*state)[HID] = (t & 1) ? g_stateB : g_stateA;
    int cb = blockIdx.x, ks = blockIdx.y;
    int tid = threadIdx.x;
    int o = cb * 128 + tid;
    bool isHH = ks >= 32;
    const float* W = isHH ? Whh : Wih;
    int k0 = (ks & 31) * 32;

    float w[32];
    {
        const float* wp = W + (size_t)k0 * HID + o;
#pragma unroll
        for (int kk = 0; kk < 32; kk++) w[kk] = wp[(size_t)kk * HID];
    }

    __shared__ float xs[32][16];   // [kk][beam]
    for (int idx = tid; idx < BEAM * 32; idx += 128) {
        int bb = idx >> 5, kk = idx & 31;
        float xv = isHH ? state[g_sel_q[bb]][k0 + kk]
                        : embed[(size_t)g_sel_c[bb] * HID + k0 + kk];
        xs[kk][bb] = xv;
    }
    __syncthreads();

    unsigned long long acc[8];
#pragma unroll
    for (int p = 0; p < 8; p++) acc[p] = 0ull;
#pragma unroll
    for (int kk = 0; kk < 32; kk++) {
        unsigned long long w2 = pack2(w[kk], w[kk]);
#pragma unroll
        for (int p = 0; p < 8; p++) {
            unsigned long long x = *(const unsigned long long*)&xs[kk][2 * p];
            fma2(acc[p], x, w2);
        }
    }
#pragma unroll
    for (int p = 0; p < 8; p++) {
        float a, b2; unpack2(acc[p], a, b2);
        g_part1[ks][2 * p][o]     = a;
        g_part1[ks][2 * p + 1][o] = b2;
    }
}

__global__ void reduce_tanh_kernel(const float* __restrict__ bias, int t) {
    float (*out)[HID] = (t & 1) ? g_stateA : g_stateB;
    int i = blockIdx.x * 256 + threadIdx.x;   // 16384 total
    int bb = i >> 10, o = i & 1023;
    float sih = 0.f, shh = 0.f;
#pragma unroll 8
    for (int ks = 0; ks < 32; ks++) sih += g_part1[ks][bb][o];
#pragma unroll 8
    for (int ks = 32; ks < 64; ks++) shh += g_part1[ks][bb][o];
    float pre = (sih + shh) + bias[o];
    out[bb][o] = tanh_acc(pre);
}

// ---------------- output projection (exact R7) ----------------
// grid 250 x 256, 64KB dynamic smem, 2 CTAs/SM
__global__ void __launch_bounds__(256, 2) gemm2_kernel(const float* __restrict__ Wout, int t) {
    extern __shared__ char smem_raw[];
    float (*xs)[16] = (float (*)[16])smem_raw;            // [1024][16] = 64KB
    const float (*h)[HID] = (t & 1) ? g_stateA : g_stateB;
    int cb  = blockIdx.x;
    int tid = threadIdx.x;
    int ksp  = tid >> 5;      // 0..7
    int colg = tid & 31;      // 0..31

    for (int idx = tid; idx < 4096; idx += 256) {
        int b = idx & 15, k4 = idx >> 4;
        float4 v = *(const float4*)&h[b][k4 * 4];
        xs[k4 * 4 + 0][b] = v.x; xs[k4 * 4 + 1][b] = v.y;
        xs[k4 * 4 + 2][b] = v.z; xs[k4 * 4 + 3][b] = v.w;
    }
    __syncthreads();

    int col = cb * G2_COLS + colg * 4;
    int k0  = ksp * G2_KC;
    unsigned long long acc[4][8];
#pragma unroll
    for (int c = 0; c < 4; c++)
#pragma unroll
        for (int p = 0; p < 8; p++) acc[c][p] = 0ull;

    const float* wp = Wout + (size_t)k0 * VOCAB + col;
    float4 wreg[4];
#pragma unroll
    for (int p = 0; p < 4; p++) wreg[p] = *(const float4*)(wp + (size_t)p * VOCAB);

    for (int kg = 0; kg < G2_KC; kg += 4) {
#pragma unroll
        for (int p = 0; p < 4; p++) {
            float4 w = wreg[p];
            if (kg + 4 + p < G2_KC)
                wreg[p] = *(const float4*)(wp + (size_t)(kg + 4 + p) * VOCAB);
            int kk = k0 + kg + p;
            unsigned long long w0 = pack2(w.x, w.x);
            unsigned long long w1 = pack2(w.y, w.y);
            unsigned long long w2 = pack2(w.z, w.z);
            unsigned long long w3 = pack2(w.w, w.w);
            const ulonglong2* xr = (const ulonglong2*)xs[kk];
            ulonglong2 qa = xr[0], qb = xr[1], qc = xr[2], qd = xr[3];
            fma2(acc[0][0], qa.x, w0); fma2(acc[1][0], qa.x, w1);
            fma2(acc[2][0], qa.x, w2); fma2(acc[3][0], qa.x, w3);
            fma2(acc[0][1], qa.y, w0); fma2(acc[1][1], qa.y, w1);
            fma2(acc[2][1], qa.y, w2); fma2(acc[3][1], qa.y, w3);
            fma2(acc[0][2], qb.x, w0); fma2(acc[1][2], qb.x, w1);
            fma2(acc[2][2], qb.x, w2); fma2(acc[3][2], qb.x, w3);
            fma2(acc[0][3], qb.y, w0); fma2(acc[1][3], qb.y, w1);
            fma2(acc[2][3], qb.y, w2); fma2(acc[3][3], qb.y, w3);
            fma2(acc[0][4], qc.x, w0); fma2(acc[1][4], qc.x, w1);
            fma2(acc[2][4], qc.x, w2); fma2(acc[3][4], qc.x, w3);
            fma2(acc[0][5], qc.y, w0); fma2(acc[1][5], qc.y, w1);
            fma2(acc[2][5], qc.y, w2); fma2(acc[3][5], qc.y, w3);
            fma2(acc[0][6], qd.x, w0); fma2(acc[1][6], qd.x, w1);
            fma2(acc[2][6], qd.x, w2); fma2(acc[3][6], qd.x, w3);
            fma2(acc[0][7], qd.y, w0); fma2(acc[1][7], qd.y, w1);
            fma2(acc[2][7], qd.y, w2); fma2(acc[3][7], qd.y, w3);
        }
    }
    __syncthreads();   // xs done; reuse smem as reduce buffer

    float (*red)[BEAM][G2_COLS] = (float (*)[BEAM][G2_COLS])smem_raw;  // [8][16][128]
#pragma unroll
    for (int c = 0; c < 4; c++) {
#pragma unroll
        for (int p = 0; p < 8; p++) {
            float a, b2; unpack2(acc[c][p], a, b2);
            red[ksp][2 * p][colg * 4 + c]     = a;
            red[ksp][2 * p + 1][colg * 4 + c] = b2;
        }
    }
    __syncthreads();

    for (int idx = tid; idx < G2_COLS * BEAM; idx += 256) {
        int b = idx >> 7, c = idx & 127;
        float s = 0.f;
#pragma unroll
        for (int k = 0; k < G2_KS; k++) s += red[k][b][c];
        g_logits[b][cb * G2_COLS + c] = s;
    }
}

// ---------------- pack outputs ----------------
__global__ void output_kernel(float* __restrict__ out, int out_size) {
    int i = blockIdx.x * 256 + threadIdx.x;
    if (i >= out_size) return;
    if (i < TSTEPS * BEAM) {
        out[i] = (float)((const int*)g_beam_seq)[i];
    } else if (i < 2 * TSTEPS * BEAM) {
        out[i] = ((const float*)g_beam_seq_lp)[i - TSTEPS * BEAM];
    } else if (i < 2 * TSTEPS * BEAM + BEAM) {
        out[i] = g_beam_lps[i - 2 * TSTEPS * BEAM];
    } else {
        out[i] = 0.f;
    }
}

extern "C" void kernel_launch(void* const* d_in, const int* in_sizes, int n_in,
                              void* d_out, int out_size) {
    const float* state    = (const float*)d_in[0];
    const float* logprobs = (const float*)d_in[1];
    const float* embed    = (const float*)d_in[2];
    const float* W_ih     = (const float*)d_in[3];
    const float* W_hh     = (const float*)d_in[4];
    const float* b        = (const float*)d_in[5];
    const float* W_out    = (const float*)d_in[6];

    cudaFuncSetAttribute(gemm2_kernel,
                         cudaFuncAttributeMaxDynamicSharedMemorySize, G2_SMEM);

    init_kernel<<<64, 256>>>(state);
    for (int t = 0; t < TSTEPS; t++) {
        dim3 gs(NCHUNK, BEAM);
        topk_scan<<<gs, 256>>>(logprobs, t);   // fast block-max scan + fused select
        if (t < TSTEPS - 1) {
            dim3 g1(8, 64);
            gemm1_kernel<<<g1, 128>>>(embed, W_ih, W_hh, t);
            reduce_tanh_kernel<<<64, 256>>>(b, t);
            gemm2_kernel<<<250, 256, G2_SMEM>>>(W_out, t);
        }
    }
    int nblk = (out_size + 255) / 256;
    if (nblk < 1) nblk = 1;
    output_kernel<<<nblk, 256>>>((float*)d_out, out_size);
}